// round 1
// baseline (speedup 1.0000x reference)
#include <cuda_runtime.h>
#include <cuda_bf16.h>
#include <math.h>

// Problem constants
#define NN 50000
#define EE 800000
#define DD 128
#define HH 8

typedef unsigned long long u64;

// ---------------- scratch (device globals; no allocation allowed) ----------------
__device__ float g_hln[(size_t)NN * DD];
__device__ float g_Q[(size_t)NN * DD];
__device__ float g_K[(size_t)NN * DD];
__device__ float g_V[(size_t)NN * DD];
__device__ float g_wV[(size_t)NN * DD];
__device__ float g_z[(size_t)NN * HH];
__device__ float g_hmid[(size_t)NN * DD];
__device__ float g_emid[(size_t)EE * DD];
__device__ float g_eattn[(size_t)EE * DD];
__device__ float g_hid_n[(size_t)NN * 256];
__device__ float g_hid_e[(size_t)EE * 256];

// ---------------- f32x2 helpers (Blackwell packed fp32 FMA) ----------------
__device__ __forceinline__ u64 pk2(float lo, float hi) {
    u64 r; asm("mov.b64 %0, {%1, %2};" : "=l"(r) : "f"(lo), "f"(hi)); return r;
}
__device__ __forceinline__ void upk2(u64 v, float& lo, float& hi) {
    asm("mov.b64 {%0, %1}, %2;" : "=f"(lo), "=f"(hi) : "l"(v));
}
__device__ __forceinline__ u64 ff2(u64 a, u64 b, u64 c) {
    u64 d; asm("fma.rn.f32x2 %0, %1, %2, %3;" : "=l"(d) : "l"(a), "l"(b), "l"(c)); return d;
}

// ---------------- LayerNorm: one warp per row of 128 ----------------
__global__ void ln_kernel(const float* __restrict__ x, const float* __restrict__ w,
                          const float* __restrict__ b, float* __restrict__ y, int M)
{
    int gw = (blockIdx.x * blockDim.x + threadIdx.x) >> 5;
    int lane = threadIdx.x & 31;
    if (gw >= M) return;
    const float4 v = *(const float4*)(x + (size_t)gw * 128 + lane * 4);
    float s = v.x + v.y + v.z + v.w;
    float ss = v.x * v.x + v.y * v.y + v.z * v.z + v.w * v.w;
#pragma unroll
    for (int o = 16; o > 0; o >>= 1) {
        s += __shfl_xor_sync(0xffffffffu, s, o);
        ss += __shfl_xor_sync(0xffffffffu, ss, o);
    }
    float m = s * (1.f / 128.f);
    float var = ss * (1.f / 128.f) - m * m;
    float rs = rsqrtf(var + 1e-5f);
    float4 w4 = ((const float4*)w)[lane];
    float4 b4 = ((const float4*)b)[lane];
    float4 o;
    o.x = (v.x - m) * rs * w4.x + b4.x;
    o.y = (v.y - m) * rs * w4.y + b4.y;
    o.z = (v.z - m) * rs * w4.z + b4.z;
    o.w = (v.w - m) * rs * w4.w + b4.w;
    *(float4*)(y + (size_t)gw * 128 + lane * 4) = o;
}

// ---------------- generic GEMM: C[M,outCols] = A[M,K] @ W[K,outCols] (+bias)(silu)(+resid) ----------------
#define F_SILU 1
#define F_BIAS 2
#define F_RESID 4
#define SMEM_GEMM ((64 * 132 + 128 * 128) * 4)

__global__ void __launch_bounds__(256) gemm_k(
    const float* __restrict__ A, const float* __restrict__ W,
    const float* __restrict__ bias, const float* __restrict__ Rin,
    float* __restrict__ C, int M, int K, int outCols, int flags)
{
    extern __shared__ float sm[];
    float* As = sm;              // 64 x 132 (padded)
    float* Bs = sm + 64 * 132;   // 128 x 128 (chunk of W)
    const int tid = threadIdx.x;
    const int ty = tid >> 4, tx = tid & 15;
    const int rowBase = blockIdx.x * 64;
    const int colBase = blockIdx.y * 128;

    u64 acc[4][4];
#pragma unroll
    for (int i = 0; i < 4; i++)
#pragma unroll
        for (int j = 0; j < 4; j++) acc[i][j] = 0ull;

    for (int kb = 0; kb < K; kb += 128) {
#pragma unroll
        for (int i = 0; i < 8; i++) {
            int f4 = tid + i * 256;
            int r = f4 >> 5, c = (f4 & 31) << 2;
            int row = rowBase + r;
            float4 v = make_float4(0.f, 0.f, 0.f, 0.f);
            if (row < M) v = *(const float4*)(A + (size_t)row * K + kb + c);
            *(float4*)(As + r * 132 + c) = v;
        }
#pragma unroll
        for (int i = 0; i < 16; i++) {
            int f4 = tid + i * 256;
            int r = f4 >> 5, c = (f4 & 31) << 2;
            *(float4*)(Bs + r * 128 + c) =
                *(const float4*)(W + (size_t)(kb + r) * outCols + colBase + c);
        }
        __syncthreads();
#pragma unroll 4
        for (int k = 0; k < 128; k++) {
            u64 a2[4];
#pragma unroll
            for (int i = 0; i < 4; i++) {
                float a = As[(ty * 4 + i) * 132 + k];
                a2[i] = pk2(a, a);
            }
            ulonglong2 bb0 = *(const ulonglong2*)(Bs + k * 128 + tx * 8);
            ulonglong2 bb1 = *(const ulonglong2*)(Bs + k * 128 + tx * 8 + 4);
            u64 b0 = bb0.x, b1 = bb0.y, b2 = bb1.x, b3 = bb1.y;
#pragma unroll
            for (int i = 0; i < 4; i++) {
                acc[i][0] = ff2(a2[i], b0, acc[i][0]);
                acc[i][1] = ff2(a2[i], b1, acc[i][1]);
                acc[i][2] = ff2(a2[i], b2, acc[i][2]);
                acc[i][3] = ff2(a2[i], b3, acc[i][3]);
            }
        }
        __syncthreads();
    }

    const int col0 = colBase + tx * 8;
    float bv[8];
#pragma unroll
    for (int j = 0; j < 8; j++) bv[j] = (flags & F_BIAS) ? bias[col0 + j] : 0.f;
#pragma unroll
    for (int i = 0; i < 4; i++) {
        int row = rowBase + ty * 4 + i;
        if (row >= M) continue;
        float o[8];
#pragma unroll
        for (int j = 0; j < 4; j++) upk2(acc[i][j], o[2 * j], o[2 * j + 1]);
#pragma unroll
        for (int j = 0; j < 8; j++) {
            float v = o[j] + bv[j];
            if (flags & F_SILU) v = v / (1.f + __expf(-v));
            if (flags & F_RESID) v += Rin[(size_t)row * outCols + col0 + j];
            o[j] = v;
        }
        *(float4*)(C + (size_t)row * outCols + col0) = make_float4(o[0], o[1], o[2], o[3]);
        *(float4*)(C + (size_t)row * outCols + col0 + 4) = make_float4(o[4], o[5], o[6], o[7]);
    }
}

// ---------------- fused edge attention ----------------
// Per 64-edge block: LN(edge rows) -> proj = LN @ We + be -> score/e_out -> w -> scatter.
__global__ void __launch_bounds__(256) attn_edge_kernel(
    const float* __restrict__ ef, const float* __restrict__ lnw, const float* __restrict__ lnb,
    const float* __restrict__ We, const float* __restrict__ be,
    const float* __restrict__ Qm, const float* __restrict__ Km, const float* __restrict__ Vm,
    const int* __restrict__ src, const int* __restrict__ dst,
    float* __restrict__ eout, float* __restrict__ wV, float* __restrict__ z)
{
    extern __shared__ float sm[];
    float* As = sm;              // 64 x 132 (LN'd edge rows)
    float* Bs = sm + 64 * 132;   // 128 x 128 (We)
    const int tid = threadIdx.x;
    const int lane = tid & 31;
    const int warp = tid >> 5;
    const size_t e0 = (size_t)blockIdx.x * 64;

    // load We
#pragma unroll
    for (int i = 0; i < 16; i++) {
        int f4 = tid + i * 256;
        int r = f4 >> 5, c = (f4 & 31) << 2;
        *(float4*)(Bs + r * 128 + c) = *(const float4*)(We + (size_t)r * 128 + c);
    }

    // LN: warp handles 8 rows
    float4 w4 = ((const float4*)lnw)[lane];
    float4 b4 = ((const float4*)lnb)[lane];
#pragma unroll
    for (int rr = 0; rr < 8; rr++) {
        int r = warp * 8 + rr;
        const float4 v = *(const float4*)(ef + (e0 + r) * 128 + lane * 4);
        float s = v.x + v.y + v.z + v.w;
        float ss = v.x * v.x + v.y * v.y + v.z * v.z + v.w * v.w;
#pragma unroll
        for (int o = 16; o > 0; o >>= 1) {
            s += __shfl_xor_sync(0xffffffffu, s, o);
            ss += __shfl_xor_sync(0xffffffffu, ss, o);
        }
        float m = s * (1.f / 128.f);
        float var = ss * (1.f / 128.f) - m * m;
        float rs = rsqrtf(var + 1e-5f);
        float4 o;
        o.x = (v.x - m) * rs * w4.x + b4.x;
        o.y = (v.y - m) * rs * w4.y + b4.y;
        o.z = (v.z - m) * rs * w4.z + b4.z;
        o.w = (v.w - m) * rs * w4.w + b4.w;
        *(float4*)(As + r * 132 + lane * 4) = o;
    }
    __syncthreads();

    // GEMM: proj = As @ We
    const int ty = tid >> 4, tx = tid & 15;
    u64 acc[4][4];
#pragma unroll
    for (int i = 0; i < 4; i++)
#pragma unroll
        for (int j = 0; j < 4; j++) acc[i][j] = 0ull;
#pragma unroll 4
    for (int k = 0; k < 128; k++) {
        u64 a2[4];
#pragma unroll
        for (int i = 0; i < 4; i++) {
            float a = As[(ty * 4 + i) * 132 + k];
            a2[i] = pk2(a, a);
        }
        ulonglong2 bb0 = *(const ulonglong2*)(Bs + k * 128 + tx * 8);
        ulonglong2 bb1 = *(const ulonglong2*)(Bs + k * 128 + tx * 8 + 4);
        u64 b0 = bb0.x, b1 = bb0.y, b2 = bb1.x, b3 = bb1.y;
#pragma unroll
        for (int i = 0; i < 4; i++) {
            acc[i][0] = ff2(a2[i], b0, acc[i][0]);
            acc[i][1] = ff2(a2[i], b1, acc[i][1]);
            acc[i][2] = ff2(a2[i], b2, acc[i][2]);
            acc[i][3] = ff2(a2[i], b3, acc[i][3]);
        }
    }

    const int c0 = tx * 8;
    const int head = tx >> 1;
    float be8[8];
#pragma unroll
    for (int j = 0; j < 8; j++) be8[j] = be[c0 + j];

#pragma unroll
    for (int i = 0; i < 4; i++) {
        size_t e = e0 + (size_t)ty * 4 + i;
        float pj[8];
#pragma unroll
        for (int j = 0; j < 4; j++) upk2(acc[i][j], pj[2 * j], pj[2 * j + 1]);
#pragma unroll
        for (int j = 0; j < 8; j++) pj[j] += be8[j];

        int sN = src[e], dN = dst[e];
        float4 k0 = *(const float4*)(Km + (size_t)sN * 128 + c0);
        float4 k1 = *(const float4*)(Km + (size_t)sN * 128 + c0 + 4);
        float4 q0 = *(const float4*)(Qm + (size_t)dN * 128 + c0);
        float4 q1 = *(const float4*)(Qm + (size_t)dN * 128 + c0 + 4);
        float kk[8] = {k0.x, k0.y, k0.z, k0.w, k1.x, k1.y, k1.z, k1.w};
        float qq[8] = {q0.x, q0.y, q0.z, q0.w, q1.x, q1.y, q1.z, q1.w};
        float eo[8];
        float sum = 0.f;
#pragma unroll
        for (int j = 0; j < 8; j++) {
            float sc = kk[j] * qq[j] * 0.25f;
            sc = fminf(5.f, fmaxf(-5.f, sc));
            eo[j] = sc * pj[j];
            sum += eo[j];
        }
        *(float4*)(eout + e * 128 + c0) = make_float4(eo[0], eo[1], eo[2], eo[3]);
        *(float4*)(eout + e * 128 + c0 + 4) = make_float4(eo[4], eo[5], eo[6], eo[7]);

        sum += __shfl_xor_sync(0xffffffffu, sum, 1);  // pair over the 16-wide head
        float wgt = __expf(fminf(5.f, fmaxf(-5.f, sum)));

        float4 v0 = *(const float4*)(Vm + (size_t)sN * 128 + c0);
        float4 v1 = *(const float4*)(Vm + (size_t)sN * 128 + c0 + 4);
        float* wd = wV + (size_t)dN * 128 + c0;
        atomicAdd(wd + 0, v0.x * wgt);
        atomicAdd(wd + 1, v0.y * wgt);
        atomicAdd(wd + 2, v0.z * wgt);
        atomicAdd(wd + 3, v0.w * wgt);
        atomicAdd(wd + 4, v1.x * wgt);
        atomicAdd(wd + 5, v1.y * wgt);
        atomicAdd(wd + 6, v1.z * wgt);
        atomicAdd(wd + 7, v1.w * wgt);
        if (!(tx & 1)) atomicAdd(z + (size_t)dN * 8 + head, wgt);
    }
}

// ---------------- h_attn = wV / (z + 1e-8) ----------------
__global__ void finalize_attn(const float* __restrict__ wV, const float* __restrict__ z,
                              float* __restrict__ hattn)
{
    int idx = blockIdx.x * blockDim.x + threadIdx.x;  // per float4
    if (idx >= NN * 32) return;
    int n = idx >> 5;
    int q = idx & 31;
    int head = q >> 2;
    float inv = 1.f / (z[(size_t)n * 8 + head] + 1e-8f);
    float4 v = ((const float4*)wV)[idx];
    v.x *= inv; v.y *= inv; v.z *= inv; v.w *= inv;
    ((float4*)hattn)[idx] = v;
}

// ---------------- launch ----------------
extern "C" void kernel_launch(void* const* d_in, const int* in_sizes, int n_in,
                              void* d_out, int out_size)
{
    const float* node_feats = (const float*)d_in[0];
    const float* edge_feats = (const float*)d_in[1];
    const int*   src        = (const int*)d_in[2];
    const int*   dst        = (const int*)d_in[3];
    const float* ln1n_w = (const float*)d_in[4];
    const float* ln1n_b = (const float*)d_in[5];
    const float* ln1e_w = (const float*)d_in[6];
    const float* ln1e_b = (const float*)d_in[7];
    const float* ln2n_w = (const float*)d_in[8];
    const float* ln2n_b = (const float*)d_in[9];
    const float* ln2e_w = (const float*)d_in[10];
    const float* ln2e_b = (const float*)d_in[11];
    const float* Wq = (const float*)d_in[12];
    const float* bq = (const float*)d_in[13];
    const float* Wk = (const float*)d_in[14];
    const float* bk = (const float*)d_in[15];
    const float* Wv = (const float*)d_in[16];
    const float* bv = (const float*)d_in[17];
    const float* We = (const float*)d_in[18];
    const float* be = (const float*)d_in[19];
    const float* Wo_n = (const float*)d_in[20];
    const float* bo_n = (const float*)d_in[21];
    const float* Wo_e = (const float*)d_in[22];
    const float* bo_e = (const float*)d_in[23];
    const float* mlp_n_w1 = (const float*)d_in[24];
    const float* mlp_n_w2 = (const float*)d_in[25];
    const float* mlp_e_w1 = (const float*)d_in[26];
    const float* mlp_e_w2 = (const float*)d_in[27];

    float* outh = (float*)d_out;
    float* oute = outh + (size_t)NN * DD;

    float *p_hln, *p_Q, *p_K, *p_V, *p_wV, *p_z, *p_hmid, *p_emid, *p_eattn, *p_hidn, *p_hide;
    cudaGetSymbolAddress((void**)&p_hln, g_hln);
    cudaGetSymbolAddress((void**)&p_Q, g_Q);
    cudaGetSymbolAddress((void**)&p_K, g_K);
    cudaGetSymbolAddress((void**)&p_V, g_V);
    cudaGetSymbolAddress((void**)&p_wV, g_wV);
    cudaGetSymbolAddress((void**)&p_z, g_z);
    cudaGetSymbolAddress((void**)&p_hmid, g_hmid);
    cudaGetSymbolAddress((void**)&p_emid, g_emid);
    cudaGetSymbolAddress((void**)&p_eattn, g_eattn);
    cudaGetSymbolAddress((void**)&p_hidn, g_hid_n);
    cudaGetSymbolAddress((void**)&p_hide, g_hid_e);

    cudaFuncSetAttribute(gemm_k, cudaFuncAttributeMaxDynamicSharedMemorySize, SMEM_GEMM);
    cudaFuncSetAttribute(attn_edge_kernel, cudaFuncAttributeMaxDynamicSharedMemorySize, SMEM_GEMM);

    // zero scatter accumulators
    cudaMemsetAsync(p_wV, 0, (size_t)NN * DD * sizeof(float));
    cudaMemsetAsync(p_z, 0, (size_t)NN * HH * sizeof(float));

    const int lnThreads = 256;
    dim3 blk(256);

    // 1) LN nodes -> g_hln
    ln_kernel<<<(NN * 32 + lnThreads - 1) / lnThreads, lnThreads>>>(node_feats, ln1n_w, ln1n_b, p_hln, NN);

    // 2) Q/K/V projections
    int gN = (NN + 63) / 64;
    gemm_k<<<dim3(gN, 1), blk, SMEM_GEMM>>>(p_hln, Wq, bq, nullptr, p_Q, NN, 128, 128, F_BIAS);
    gemm_k<<<dim3(gN, 1), blk, SMEM_GEMM>>>(p_hln, Wk, bk, nullptr, p_K, NN, 128, 128, F_BIAS);
    gemm_k<<<dim3(gN, 1), blk, SMEM_GEMM>>>(p_hln, Wv, bv, nullptr, p_V, NN, 128, 128, F_BIAS);

    // 3) fused edge attention: LN1e + @We+be + score + e_out + scatter
    attn_edge_kernel<<<EE / 64, blk, SMEM_GEMM>>>(edge_feats, ln1e_w, ln1e_b, We, be,
                                                  p_Q, p_K, p_V, src, dst,
                                                  p_eattn, p_wV, p_z);

    // 4) node attention output + Wo_n + residual
    finalize_attn<<<(NN * 32 + 255) / 256, 256>>>(p_wV, p_z, p_hln);
    gemm_k<<<dim3(gN, 1), blk, SMEM_GEMM>>>(p_hln, Wo_n, bo_n, node_feats, p_hmid, NN, 128, 128, F_BIAS | F_RESID);

    // 5) node FFN
    ln_kernel<<<(NN * 32 + lnThreads - 1) / lnThreads, lnThreads>>>(p_hmid, ln2n_w, ln2n_b, p_hln, NN);
    gemm_k<<<dim3(gN, 2), blk, SMEM_GEMM>>>(p_hln, mlp_n_w1, nullptr, nullptr, p_hidn, NN, 128, 256, F_SILU);
    gemm_k<<<dim3(gN, 1), blk, SMEM_GEMM>>>(p_hidn, mlp_n_w2, nullptr, p_hmid, outh, NN, 256, 128, F_RESID);

    // 6) edge output projection + residual
    int gE = EE / 64;
    gemm_k<<<dim3(gE, 1), blk, SMEM_GEMM>>>(p_eattn, Wo_e, bo_e, edge_feats, p_emid, EE, 128, 128, F_BIAS | F_RESID);

    // 7) edge FFN
    ln_kernel<<<((size_t)EE * 32 + lnThreads - 1) / lnThreads, lnThreads>>>(p_emid, ln2e_w, ln2e_b, p_eattn, EE);
    gemm_k<<<dim3(gE, 2), blk, SMEM_GEMM>>>(p_eattn, mlp_e_w1, nullptr, nullptr, p_hide, EE, 128, 256, F_SILU);
    gemm_k<<<dim3(gE, 1), blk, SMEM_GEMM>>>(p_hide, mlp_e_w2, nullptr, p_emid, oute, EE, 256, 128, F_RESID);
}

// round 4
// speedup vs baseline: 1.1760x; 1.1760x over previous
#include <cuda_runtime.h>
#include <cuda_bf16.h>
#include <mma.h>
#include <math.h>
#include <cstdint>

using namespace nvcuda;

#define NN 50000
#define EE 800000
#define DD 128
#define HH 8

typedef unsigned int u32;

// ---------------- scratch (device globals) ----------------
__device__ float g_Q[(size_t)NN * DD];
__device__ float g_K[(size_t)NN * DD];
__device__ float g_V[(size_t)NN * DD];
__device__ float g_wV[(size_t)NN * DD];
__device__ float g_z[(size_t)NN * HH];
__device__ float g_hattn[(size_t)NN * DD];
__device__ float g_hmid[(size_t)NN * DD];
__device__ float g_emid[(size_t)EE * DD];
__device__ float g_eattn[(size_t)EE * DD];
__device__ float g_hid_n[(size_t)NN * 256];
__device__ float g_hid_e[(size_t)EE * 256];

__device__ __forceinline__ float tf32r(float x) {
    u32 u; asm("cvt.rna.tf32.f32 %0, %1;" : "=r"(u) : "f"(x));
    return __uint_as_float(u);
}

#define TS 136                       // padded smem row stride (floats)
#define AS_FLOATS (128 * TS)         // 17408
#define SMEM_BYTES (2 * AS_FLOATS * 4)  // 139264

#define F_SILU 1
#define F_BIAS 2
#define F_RESID 4
#define F_LN 8

typedef wmma::fragment<wmma::matrix_a, 16, 16, 8, wmma::precision::tf32, wmma::row_major> FragA;
typedef wmma::fragment<wmma::matrix_b, 16, 16, 8, wmma::precision::tf32, wmma::row_major> FragB;
typedef wmma::fragment<wmma::accumulator, 16, 16, 8, float> FragC;

// ---- staging helpers ----
__device__ __forceinline__ void stage_ln(const float* __restrict__ A,
                                         const float* __restrict__ lnw,
                                         const float* __restrict__ lnb,
                                         float* As, int rowBase, int M,
                                         int w, int lane)
{
    float4 w4 = ((const float4*)lnw)[lane];
    float4 b4 = ((const float4*)lnb)[lane];
#pragma unroll
    for (int rr = 0; rr < 16; rr++) {
        int r = w * 16 + rr;
        int row = rowBase + r;
        float4 v = make_float4(0.f, 0.f, 0.f, 0.f);
        if (row < M) {
            v = *(const float4*)(A + (size_t)row * 128 + lane * 4);
            float s = v.x + v.y + v.z + v.w;
            float ss = v.x * v.x + v.y * v.y + v.z * v.z + v.w * v.w;
#pragma unroll
            for (int o = 16; o > 0; o >>= 1) {
                s += __shfl_xor_sync(0xffffffffu, s, o);
                ss += __shfl_xor_sync(0xffffffffu, ss, o);
            }
            float m = s * (1.f / 128.f);
            float var = ss * (1.f / 128.f) - m * m;
            float rs = rsqrtf(var + 1e-5f);
            v.x = (v.x - m) * rs * w4.x + b4.x;
            v.y = (v.y - m) * rs * w4.y + b4.y;
            v.z = (v.z - m) * rs * w4.z + b4.z;
            v.w = (v.w - m) * rs * w4.w + b4.w;
        }
        *(float4*)(As + r * TS + lane * 4) =
            make_float4(tf32r(v.x), tf32r(v.y), tf32r(v.z), tf32r(v.w));
    }
}

__device__ __forceinline__ void stage_plain(const float* __restrict__ A,
                                            float* As, int rowBase, int M,
                                            int K, int kb, int tid)
{
#pragma unroll
    for (int it = 0; it < 16; it++) {
        int f = tid + it * 256;
        int r = f >> 5;
        int c = (f & 31) << 2;
        int row = rowBase + r;
        float4 v = make_float4(0.f, 0.f, 0.f, 0.f);
        if (row < M) v = *(const float4*)(A + (size_t)row * K + kb + c);
        *(float4*)(As + r * TS + c) =
            make_float4(tf32r(v.x), tf32r(v.y), tf32r(v.z), tf32r(v.w));
    }
}

// stage 128 rows of W[K,outCols], col slab [colBase, colBase+128)
__device__ __forceinline__ void stage_W(const float* __restrict__ W,
                                        float* Bs, int kb, int outCols, int colBase, int tid)
{
#pragma unroll
    for (int it = 0; it < 16; it++) {
        int f = tid + it * 256;
        int r = f >> 5;
        int c = (f & 31) << 2;
        float4 v = *(const float4*)(W + (size_t)(kb + r) * outCols + colBase + c);
        *(float4*)(Bs + r * TS + c) =
            make_float4(tf32r(v.x), tf32r(v.y), tf32r(v.z), tf32r(v.w));
    }
}

__device__ __forceinline__ void mma_chunk(const float* As, const float* Bs,
                                          int wm, int wn, FragC acc[2][4])
{
#pragma unroll
    for (int kk = 0; kk < 128; kk += 8) {
        FragA fa[2];
        FragB fb[4];
#pragma unroll
        for (int i = 0; i < 2; i++)
            wmma::load_matrix_sync(fa[i], As + (wm * 32 + i * 16) * TS + kk, TS);
#pragma unroll
        for (int j = 0; j < 4; j++)
            wmma::load_matrix_sync(fb[j], Bs + kk * TS + wn * 64 + j * 16, TS);
#pragma unroll
        for (int i = 0; i < 2; i++)
#pragma unroll
            for (int j = 0; j < 4; j++)
                wmma::mma_sync(acc[i][j], fa[i], fb[j], acc[i][j]);
    }
}

// ---------------- generic GEMM: C[M,outCols] = op(A) @ W ----------------
__global__ void __launch_bounds__(256) gemm_tc(
    const float* __restrict__ A, const float* __restrict__ W,
    const float* __restrict__ bias, const float* __restrict__ lnw, const float* __restrict__ lnb,
    const float* __restrict__ Rin, float* __restrict__ C,
    int M, int K, int outCols, int flags)
{
    extern __shared__ float sm[];
    float* As = sm;
    float* Bs = sm + AS_FLOATS;
    const int tid = threadIdx.x;
    const int w = tid >> 5, lane = tid & 31;
    const int wm = w & 3, wn = w >> 2;
    const int rowBase = blockIdx.x * 128;
    const int colBase = blockIdx.y * 128;

    FragC acc[2][4];
#pragma unroll
    for (int i = 0; i < 2; i++)
#pragma unroll
        for (int j = 0; j < 4; j++) wmma::fill_fragment(acc[i][j], 0.f);

    const int nchunk = K >> 7;
    for (int ch = 0; ch < nchunk; ch++) {
        stage_W(W, Bs, ch * 128, outCols, colBase, tid);
        if (flags & F_LN) stage_ln(A, lnw, lnb, As, rowBase, M, w, lane);
        else stage_plain(A, As, rowBase, M, K, ch * 128, tid);
        __syncthreads();
        mma_chunk(As, Bs, wm, wn, acc);
        __syncthreads();
    }

    // dump accumulators to smem (reuse As)
#pragma unroll
    for (int i = 0; i < 2; i++)
#pragma unroll
        for (int j = 0; j < 4; j++)
            wmma::store_matrix_sync(As + (wm * 32 + i * 16) * TS + wn * 64 + j * 16,
                                    acc[i][j], TS, wmma::mem_row_major);
    __syncthreads();

    // epilogue: 2 threads per row
    const int r = tid >> 1;
    const int halfsel = tid & 1;
    const int row = rowBase + r;
    if (row < M) {
#pragma unroll
        for (int c4 = 0; c4 < 16; c4++) {
            int c = halfsel * 64 + c4 * 4;
            float4 v = *(const float4*)(As + r * TS + c);
            int gc = colBase + c;
            if (flags & F_BIAS) {
                float4 bv = *(const float4*)(bias + gc);
                v.x += bv.x; v.y += bv.y; v.z += bv.z; v.w += bv.w;
            }
            if (flags & F_SILU) {
                v.x = v.x / (1.f + __expf(-v.x));
                v.y = v.y / (1.f + __expf(-v.y));
                v.z = v.z / (1.f + __expf(-v.z));
                v.w = v.w / (1.f + __expf(-v.w));
            }
            if (flags & F_RESID) {
                float4 rv = *(const float4*)(Rin + (size_t)row * outCols + gc);
                v.x += rv.x; v.y += rv.y; v.z += rv.z; v.w += rv.w;
            }
            *(float4*)(C + (size_t)row * outCols + gc) = v;
        }
    }
}

// ---------------- fused edge attention ----------------
__global__ void __launch_bounds__(256) attn_tc(
    const float* __restrict__ ef, const float* __restrict__ We,
    const float* __restrict__ lnw, const float* __restrict__ lnb,
    const float* __restrict__ be,
    const float* __restrict__ Qm, const float* __restrict__ Km, const float* __restrict__ Vm,
    const int* __restrict__ src, const int* __restrict__ dst,
    float* __restrict__ eout, float* __restrict__ wV, float* __restrict__ z)
{
    extern __shared__ float sm[];
    float* As = sm;
    float* Bs = sm + AS_FLOATS;
    float* proj = sm;  // reuse As after mainloop
    const int tid = threadIdx.x;
    const int w = tid >> 5, lane = tid & 31;
    const int wm = w & 3, wn = w >> 2;
    const int rowBase = blockIdx.x * 128;

    FragC acc[2][4];
#pragma unroll
    for (int i = 0; i < 2; i++)
#pragma unroll
        for (int j = 0; j < 4; j++) wmma::fill_fragment(acc[i][j], 0.f);

    stage_W(We, Bs, 0, 128, 0, tid);
    stage_ln(ef, lnw, lnb, As, rowBase, EE, w, lane);
    __syncthreads();
    mma_chunk(As, Bs, wm, wn, acc);
    __syncthreads();

#pragma unroll
    for (int i = 0; i < 2; i++)
#pragma unroll
        for (int j = 0; j < 4; j++)
            wmma::store_matrix_sync(proj + (wm * 32 + i * 16) * TS + wn * 64 + j * 16,
                                    acc[i][j], TS, wmma::mem_row_major);
    __syncthreads();

    // per-edge epilogue: 2 threads per edge, 4 heads each
    const int r = tid >> 1;
    const int h0 = (tid & 1) * 4;
    const size_t e = (size_t)rowBase + r;
    const int sN = src[e], dN = dst[e];
    const float* Kp = Km + (size_t)sN * 128;
    const float* Qp = Qm + (size_t)dN * 128;
    const float* Vp = Vm + (size_t)sN * 128;
    float* wd = wV + (size_t)dN * 128;

#pragma unroll
    for (int h = h0; h < h0 + 4; h++) {
        const int c0 = h * 16;
        float sum = 0.f;
#pragma unroll
        for (int q4 = 0; q4 < 4; q4++) {
            float4 p = *(const float4*)(proj + r * TS + c0 + q4 * 4);
            float4 bv = *(const float4*)(be + c0 + q4 * 4);
            p.x += bv.x; p.y += bv.y; p.z += bv.z; p.w += bv.w;
            float4 kk = *(const float4*)(Kp + c0 + q4 * 4);
            float4 qq = *(const float4*)(Qp + c0 + q4 * 4);
            float s0 = fminf(5.f, fmaxf(-5.f, kk.x * qq.x * 0.25f));
            float s1 = fminf(5.f, fmaxf(-5.f, kk.y * qq.y * 0.25f));
            float s2 = fminf(5.f, fmaxf(-5.f, kk.z * qq.z * 0.25f));
            float s3 = fminf(5.f, fmaxf(-5.f, kk.w * qq.w * 0.25f));
            float4 eo = make_float4(s0 * p.x, s1 * p.y, s2 * p.z, s3 * p.w);
            sum += eo.x + eo.y + eo.z + eo.w;
            *(float4*)(eout + e * 128 + c0 + q4 * 4) = eo;
        }
        float wgt = __expf(fminf(5.f, fmaxf(-5.f, sum)));
#pragma unroll
        for (int q4 = 0; q4 < 4; q4++) {
            float4 vv = *(const float4*)(Vp + c0 + q4 * 4);
            atomicAdd(wd + c0 + q4 * 4 + 0, vv.x * wgt);
            atomicAdd(wd + c0 + q4 * 4 + 1, vv.y * wgt);
            atomicAdd(wd + c0 + q4 * 4 + 2, vv.z * wgt);
            atomicAdd(wd + c0 + q4 * 4 + 3, vv.w * wgt);
        }
        atomicAdd(z + (size_t)dN * 8 + h, wgt);
    }
}

// ---------------- h_attn = wV / (z + 1e-8) ----------------
__global__ void finalize_attn(const float* __restrict__ wV, const float* __restrict__ z,
                              float* __restrict__ hattn)
{
    int idx = blockIdx.x * blockDim.x + threadIdx.x;
    if (idx >= NN * 32) return;
    int n = idx >> 5;
    int head = (idx & 31) >> 2;
    float inv = 1.f / (z[(size_t)n * 8 + head] + 1e-8f);
    float4 v = ((const float4*)wV)[idx];
    v.x *= inv; v.y *= inv; v.z *= inv; v.w *= inv;
    ((float4*)hattn)[idx] = v;
}

// ---------------- launch ----------------
extern "C" void kernel_launch(void* const* d_in, const int* in_sizes, int n_in,
                              void* d_out, int out_size)
{
    const float* node_feats = (const float*)d_in[0];
    const float* edge_feats = (const float*)d_in[1];
    const int*   src        = (const int*)d_in[2];
    const int*   dst        = (const int*)d_in[3];
    const float* ln1n_w = (const float*)d_in[4];
    const float* ln1n_b = (const float*)d_in[5];
    const float* ln1e_w = (const float*)d_in[6];
    const float* ln1e_b = (const float*)d_in[7];
    const float* ln2n_w = (const float*)d_in[8];
    const float* ln2n_b = (const float*)d_in[9];
    const float* ln2e_w = (const float*)d_in[10];
    const float* ln2e_b = (const float*)d_in[11];
    const float* Wq = (const float*)d_in[12];
    const float* bq = (const float*)d_in[13];
    const float* Wk = (const float*)d_in[14];
    const float* bk = (const float*)d_in[15];
    const float* Wv = (const float*)d_in[16];
    const float* bv = (const float*)d_in[17];
    const float* We = (const float*)d_in[18];
    const float* be = (const float*)d_in[19];
    const float* Wo_n = (const float*)d_in[20];
    const float* bo_n = (const float*)d_in[21];
    const float* Wo_e = (const float*)d_in[22];
    const float* bo_e = (const float*)d_in[23];
    const float* mlp_n_w1 = (const float*)d_in[24];
    const float* mlp_n_w2 = (const float*)d_in[25];
    const float* mlp_e_w1 = (const float*)d_in[26];
    const float* mlp_e_w2 = (const float*)d_in[27];

    float* outh = (float*)d_out;
    float* oute = outh + (size_t)NN * DD;

    float *p_Q, *p_K, *p_V, *p_wV, *p_z, *p_hattn, *p_hmid, *p_emid, *p_eattn, *p_hidn, *p_hide;
    cudaGetSymbolAddress((void**)&p_Q, g_Q);
    cudaGetSymbolAddress((void**)&p_K, g_K);
    cudaGetSymbolAddress((void**)&p_V, g_V);
    cudaGetSymbolAddress((void**)&p_wV, g_wV);
    cudaGetSymbolAddress((void**)&p_z, g_z);
    cudaGetSymbolAddress((void**)&p_hattn, g_hattn);
    cudaGetSymbolAddress((void**)&p_hmid, g_hmid);
    cudaGetSymbolAddress((void**)&p_emid, g_emid);
    cudaGetSymbolAddress((void**)&p_eattn, g_eattn);
    cudaGetSymbolAddress((void**)&p_hidn, g_hid_n);
    cudaGetSymbolAddress((void**)&p_hide, g_hid_e);

    cudaFuncSetAttribute(gemm_tc, cudaFuncAttributeMaxDynamicSharedMemorySize, SMEM_BYTES);
    cudaFuncSetAttribute(attn_tc, cudaFuncAttributeMaxDynamicSharedMemorySize, SMEM_BYTES);

    cudaMemsetAsync(p_wV, 0, (size_t)NN * DD * sizeof(float));
    cudaMemsetAsync(p_z, 0, (size_t)NN * HH * sizeof(float));

    const int gN = (NN + 127) / 128;   // 391
    const int gE = EE / 128;           // 6250

    // QKV (LN1n fused)
    gemm_tc<<<dim3(gN, 1), 256, SMEM_BYTES>>>(node_feats, Wq, bq, ln1n_w, ln1n_b, nullptr, p_Q, NN, 128, 128, F_BIAS | F_LN);
    gemm_tc<<<dim3(gN, 1), 256, SMEM_BYTES>>>(node_feats, Wk, bk, ln1n_w, ln1n_b, nullptr, p_K, NN, 128, 128, F_BIAS | F_LN);
    gemm_tc<<<dim3(gN, 1), 256, SMEM_BYTES>>>(node_feats, Wv, bv, ln1n_w, ln1n_b, nullptr, p_V, NN, 128, 128, F_BIAS | F_LN);

    // fused edge attention
    attn_tc<<<gE, 256, SMEM_BYTES>>>(edge_feats, We, ln1e_w, ln1e_b, be,
                                     p_Q, p_K, p_V, src, dst, p_eattn, p_wV, p_z);

    finalize_attn<<<(NN * 32 + 255) / 256, 256>>>(p_wV, p_z, p_hattn);

    // node: Wo_n + resid ; MLP (LN2n fused into w1)
    gemm_tc<<<dim3(gN, 1), 256, SMEM_BYTES>>>(p_hattn, Wo_n, bo_n, nullptr, nullptr, node_feats, p_hmid, NN, 128, 128, F_BIAS | F_RESID);
    gemm_tc<<<dim3(gN, 2), 256, SMEM_BYTES>>>(p_hmid, mlp_n_w1, nullptr, ln2n_w, ln2n_b, nullptr, p_hidn, NN, 128, 256, F_SILU | F_LN);
    gemm_tc<<<dim3(gN, 1), 256, SMEM_BYTES>>>(p_hidn, mlp_n_w2, nullptr, nullptr, nullptr, p_hmid, outh, NN, 256, 128, F_RESID);

    // edge: Wo_e + resid ; MLP (LN2e fused into w1)
    gemm_tc<<<dim3(gE, 1), 256, SMEM_BYTES>>>(p_eattn, Wo_e, bo_e, nullptr, nullptr, edge_feats, p_emid, EE, 128, 128, F_BIAS | F_RESID);
    gemm_tc<<<dim3(gE, 2), 256, SMEM_BYTES>>>(p_emid, mlp_e_w1, nullptr, ln2e_w, ln2e_b, nullptr, p_hide, EE, 128, 256, F_SILU | F_LN);
    gemm_tc<<<dim3(gE, 1), 256, SMEM_BYTES>>>(p_hide, mlp_e_w2, nullptr, nullptr, nullptr, p_emid, oute, EE, 256, 128, F_RESID);
}

// round 5
// speedup vs baseline: 1.2481x; 1.0614x over previous
#include <cuda_runtime.h>
#include <cuda_bf16.h>
#include <mma.h>
#include <math.h>
#include <cstdint>

using namespace nvcuda;

#define NN 50000
#define EE 800000
#define DD 128
#define HH 8

typedef unsigned int u32;

// ---------------- scratch ----------------
__device__ float g_Q[(size_t)NN * DD];
__device__ float g_K[(size_t)NN * DD];
__device__ float g_V[(size_t)NN * DD];
__device__ float g_wV[(size_t)NN * DD];
__device__ float g_z[(size_t)NN * HH];
__device__ float g_hattn[(size_t)NN * DD];
__device__ float g_hmid[(size_t)NN * DD];
__device__ float g_emid[(size_t)EE * DD];
__device__ float g_hid_n[(size_t)NN * 256];
__device__ float g_hid_e[(size_t)EE * 256];
__device__ float g_wT[229376];  // tf32-rounded weights, natural [K,N] layout

#define OT_WQ   0
#define OT_WK   16384
#define OT_WV   32768
#define OT_WON  49152
#define OT_WOE  65536
#define OT_WE   81920
#define OT_W1N  98304
#define OT_W2N  131072
#define OT_W1E  163840
#define OT_W2E  196608

__device__ __forceinline__ float tf32r(float x) {
    u32 u; asm("cvt.rna.tf32.f32 %0, %1;" : "=r"(u) : "f"(x));
    return __uint_as_float(u);
}

#define TS 132
#define AS_FLOATS (128 * TS)            // 16896
#define SMEM_1 (AS_FLOATS * 4)          // 67584
#define SMEM_2 (2 * AS_FLOATS * 4)      // 135168 (qkv kernel)

#define F_SILU 1
#define F_BIAS 2
#define F_RESID 4
#define F_LN 8

typedef wmma::fragment<wmma::matrix_a, 16, 16, 8, wmma::precision::tf32, wmma::row_major> FragA;
typedef wmma::fragment<wmma::matrix_b, 16, 16, 8, wmma::precision::tf32, wmma::row_major> FragB;
typedef wmma::fragment<wmma::accumulator, 16, 16, 8, float> FragC;

// ---- staging (4 warps / 128 threads) ----
__device__ __forceinline__ void stage_ln4(const float* __restrict__ A,
                                          const float* __restrict__ lnw,
                                          const float* __restrict__ lnb,
                                          float* As, int rowBase, int M,
                                          int w, int lane)
{
    float4 w4 = ((const float4*)lnw)[lane];
    float4 b4 = ((const float4*)lnb)[lane];
#pragma unroll
    for (int rr = 0; rr < 32; rr++) {
        int r = w * 32 + rr;
        int row = rowBase + r;
        float4 v = make_float4(0.f, 0.f, 0.f, 0.f);
        if (row < M) {
            v = *(const float4*)(A + (size_t)row * 128 + lane * 4);
            float s = v.x + v.y + v.z + v.w;
            float ss = v.x * v.x + v.y * v.y + v.z * v.z + v.w * v.w;
#pragma unroll
            for (int o = 16; o > 0; o >>= 1) {
                s += __shfl_xor_sync(0xffffffffu, s, o);
                ss += __shfl_xor_sync(0xffffffffu, ss, o);
            }
            float m = s * (1.f / 128.f);
            float var = ss * (1.f / 128.f) - m * m;
            float rs = rsqrtf(var + 1e-5f);
            v.x = (v.x - m) * rs * w4.x + b4.x;
            v.y = (v.y - m) * rs * w4.y + b4.y;
            v.z = (v.z - m) * rs * w4.z + b4.z;
            v.w = (v.w - m) * rs * w4.w + b4.w;
        }
        *(float4*)(As + r * TS + lane * 4) =
            make_float4(tf32r(v.x), tf32r(v.y), tf32r(v.z), tf32r(v.w));
    }
}

__device__ __forceinline__ void stage_plain4(const float* __restrict__ A,
                                             float* As, int rowBase, int M,
                                             int K, int kb, int tid)
{
#pragma unroll
    for (int it = 0; it < 32; it++) {
        int f = tid + it * 128;
        int r = f >> 5;
        int c = (f & 31) << 2;
        int row = rowBase + r;
        float4 v = make_float4(0.f, 0.f, 0.f, 0.f);
        if (row < M) v = *(const float4*)(A + (size_t)row * K + kb + c);
        *(float4*)(As + r * TS + c) =
            make_float4(tf32r(v.x), tf32r(v.y), tf32r(v.z), tf32r(v.w));
    }
}

// one K=128 chunk; warp computes 64x64; Bg pre-offset to (chunk_k, colBase + wn*64)
__device__ __forceinline__ void mma_loop(const float* As, const float* __restrict__ Bg,
                                         int ldB, int wm, FragC acc[4][4])
{
#pragma unroll
    for (int kk = 0; kk < 128; kk += 8) {
        FragA fa[4];
        FragB fb[4];
#pragma unroll
        for (int i = 0; i < 4; i++)
            wmma::load_matrix_sync(fa[i], As + (wm * 64 + i * 16) * TS + kk, TS);
#pragma unroll
        for (int j = 0; j < 4; j++)
            wmma::load_matrix_sync(fb[j], Bg + (size_t)kk * ldB + j * 16, ldB);
#pragma unroll
        for (int i = 0; i < 4; i++)
#pragma unroll
            for (int j = 0; j < 4; j++)
                wmma::mma_sync(acc[i][j], fa[i], fb[j], acc[i][j]);
    }
}

__device__ __forceinline__ void zero_acc(FragC acc[4][4]) {
#pragma unroll
    for (int i = 0; i < 4; i++)
#pragma unroll
        for (int j = 0; j < 4; j++) wmma::fill_fragment(acc[i][j], 0.f);
}

__device__ __forceinline__ void dump_acc(float* Cs, FragC acc[4][4], int wm, int wn) {
#pragma unroll
    for (int i = 0; i < 4; i++)
#pragma unroll
        for (int j = 0; j < 4; j++)
            wmma::store_matrix_sync(Cs + (wm * 64 + i * 16) * TS + wn * 64 + j * 16,
                                    acc[i][j], TS, wmma::mem_row_major);
}

// ---------------- generic GEMM ----------------
__global__ void __launch_bounds__(128) gemm5(
    const float* __restrict__ A, const float* __restrict__ Wt,
    const float* __restrict__ bias, const float* __restrict__ lnw, const float* __restrict__ lnb,
    const float* __restrict__ Rin, float* __restrict__ C,
    int M, int K, int outCols, int flags)
{
    extern __shared__ float As[];
    const int tid = threadIdx.x;
    const int w = tid >> 5, lane = tid & 31;
    const int wm = w >> 1, wn = w & 1;
    const int rowBase = blockIdx.x * 128;
    const int colBase = blockIdx.y * 128;

    FragC acc[4][4];
    zero_acc(acc);

    const int nchunk = K >> 7;
    for (int ch = 0; ch < nchunk; ch++) {
        if (flags & F_LN) stage_ln4(A, lnw, lnb, As, rowBase, M, w, lane);
        else stage_plain4(A, As, rowBase, M, K, ch * 128, tid);
        __syncthreads();
        mma_loop(As, Wt + (size_t)(ch * 128) * outCols + colBase + wn * 64, outCols, wm, acc);
        __syncthreads();
    }

    dump_acc(As, acc, wm, wn);
    __syncthreads();

    const int row = rowBase + tid;
    if (row < M) {
#pragma unroll
        for (int c4 = 0; c4 < 32; c4++) {
            int c = c4 * 4;
            float4 v = *(const float4*)(As + tid * TS + c);
            int gc = colBase + c;
            if (flags & F_BIAS) {
                float4 bv = *(const float4*)(bias + gc);
                v.x += bv.x; v.y += bv.y; v.z += bv.z; v.w += bv.w;
            }
            if (flags & F_SILU) {
                v.x = v.x / (1.f + __expf(-v.x));
                v.y = v.y / (1.f + __expf(-v.y));
                v.z = v.z / (1.f + __expf(-v.z));
                v.w = v.w / (1.f + __expf(-v.w));
            }
            if (flags & F_RESID) {
                float4 rv = *(const float4*)(Rin + (size_t)row * outCols + gc);
                v.x += rv.x; v.y += rv.y; v.z += rv.z; v.w += rv.w;
            }
            *(float4*)(C + (size_t)row * outCols + gc) = v;
        }
    }
}

// ---------------- QKV fused: LN(node) staged once, 3 mainloops ----------------
__global__ void __launch_bounds__(128) qkv5(
    const float* __restrict__ nf, const float* __restrict__ wT,
    const float* __restrict__ bq, const float* __restrict__ bk, const float* __restrict__ bv,
    const float* __restrict__ lnw, const float* __restrict__ lnb,
    float* __restrict__ Q, float* __restrict__ K, float* __restrict__ V)
{
    extern __shared__ float As[];
    float* Cs = As + AS_FLOATS;
    const int tid = threadIdx.x;
    const int w = tid >> 5, lane = tid & 31;
    const int wm = w >> 1, wn = w & 1;
    const int rowBase = blockIdx.x * 128;

    stage_ln4(nf, lnw, lnb, As, rowBase, NN, w, lane);
    __syncthreads();

    const float* Wts[3] = {wT + OT_WQ, wT + OT_WK, wT + OT_WV};
    const float* bs[3] = {bq, bk, bv};
    float* outs[3] = {Q, K, V};

#pragma unroll
    for (int t = 0; t < 3; t++) {
        FragC acc[4][4];
        zero_acc(acc);
        mma_loop(As, Wts[t] + wn * 64, 128, wm, acc);
        dump_acc(Cs, acc, wm, wn);
        __syncthreads();
        const int row = rowBase + tid;
        if (row < NN) {
#pragma unroll
            for (int c4 = 0; c4 < 32; c4++) {
                int c = c4 * 4;
                float4 v = *(const float4*)(Cs + tid * TS + c);
                float4 bb = *(const float4*)(bs[t] + c);
                v.x += bb.x; v.y += bb.y; v.z += bb.z; v.w += bb.w;
                *(float4*)(outs[t] + (size_t)row * 128 + c) = v;
            }
        }
        __syncthreads();
    }
}

// ---------------- fused edge attention + Wo_e ----------------
__global__ void __launch_bounds__(128) attn5(
    const float* __restrict__ ef, const float* __restrict__ WeT, const float* __restrict__ WoeT,
    const float* __restrict__ lnw, const float* __restrict__ lnb,
    const float* __restrict__ be, const float* __restrict__ boe,
    const float* __restrict__ Qm, const float* __restrict__ Km, const float* __restrict__ Vm,
    const int* __restrict__ src, const int* __restrict__ dst,
    float* __restrict__ emid, float* __restrict__ wV, float* __restrict__ z)
{
    extern __shared__ float As[];
    const int tid = threadIdx.x;
    const int w = tid >> 5, lane = tid & 31;
    const int wm = w >> 1, wn = w & 1;
    const int rowBase = blockIdx.x * 128;

    // proj = LN(ef) @ We
    stage_ln4(ef, lnw, lnb, As, rowBase, EE, w, lane);
    __syncthreads();
    FragC acc[4][4];
    zero_acc(acc);
    mma_loop(As, WeT + wn * 64, 128, wm, acc);
    __syncthreads();
    dump_acc(As, acc, wm, wn);
    __syncthreads();

    // scoring: 1 thread per edge row; eo written back in place (tf32-rounded)
    {
        const int r = tid;
        const size_t e = (size_t)rowBase + r;
        const int sN = src[e], dN = dst[e];
        const float* Kp = Km + (size_t)sN * 128;
        const float* Qp = Qm + (size_t)dN * 128;
        const float* Vp = Vm + (size_t)sN * 128;
        float* wd = wV + (size_t)dN * 128;
#pragma unroll
        for (int h = 0; h < 8; h++) {
            const int c0 = h * 16;
            float sum = 0.f;
            float4 eo[4];
#pragma unroll
            for (int q4 = 0; q4 < 4; q4++) {
                float4 p = *(const float4*)(As + r * TS + c0 + q4 * 4);
                float4 bv = *(const float4*)(be + c0 + q4 * 4);
                p.x += bv.x; p.y += bv.y; p.z += bv.z; p.w += bv.w;
                float4 kk = *(const float4*)(Kp + c0 + q4 * 4);
                float4 qq = *(const float4*)(Qp + c0 + q4 * 4);
                float s0 = fminf(5.f, fmaxf(-5.f, kk.x * qq.x * 0.25f));
                float s1 = fminf(5.f, fmaxf(-5.f, kk.y * qq.y * 0.25f));
                float s2 = fminf(5.f, fmaxf(-5.f, kk.z * qq.z * 0.25f));
                float s3 = fminf(5.f, fmaxf(-5.f, kk.w * qq.w * 0.25f));
                eo[q4] = make_float4(s0 * p.x, s1 * p.y, s2 * p.z, s3 * p.w);
                sum += eo[q4].x + eo[q4].y + eo[q4].z + eo[q4].w;
            }
#pragma unroll
            for (int q4 = 0; q4 < 4; q4++)
                *(float4*)(As + r * TS + c0 + q4 * 4) =
                    make_float4(tf32r(eo[q4].x), tf32r(eo[q4].y), tf32r(eo[q4].z), tf32r(eo[q4].w));
            float wgt = __expf(fminf(5.f, fmaxf(-5.f, sum)));
#pragma unroll
            for (int q4 = 0; q4 < 4; q4++) {
                float4 vv = *(const float4*)(Vp + c0 + q4 * 4);
                atomicAdd(wd + c0 + q4 * 4 + 0, vv.x * wgt);
                atomicAdd(wd + c0 + q4 * 4 + 1, vv.y * wgt);
                atomicAdd(wd + c0 + q4 * 4 + 2, vv.z * wgt);
                atomicAdd(wd + c0 + q4 * 4 + 3, vv.w * wgt);
            }
            atomicAdd(z + (size_t)dN * 8 + h, wgt);
        }
    }
    __syncthreads();

    // emid = eo @ Wo_e + bo_e + ef_resid
    zero_acc(acc);
    mma_loop(As, WoeT + wn * 64, 128, wm, acc);
    __syncthreads();
    dump_acc(As, acc, wm, wn);
    __syncthreads();

    const size_t row = (size_t)rowBase + tid;
#pragma unroll
    for (int c4 = 0; c4 < 32; c4++) {
        int c = c4 * 4;
        float4 v = *(const float4*)(As + tid * TS + c);
        float4 bb = *(const float4*)(boe + c);
        float4 rv = *(const float4*)(ef + row * 128 + c);
        v.x += bb.x + rv.x; v.y += bb.y + rv.y; v.z += bb.z + rv.z; v.w += bb.w + rv.w;
        *(float4*)(emid + row * 128 + c) = v;
    }
}

// ---------------- weight prep: tf32-rounded copy ----------------
__global__ void round_copy(const float* __restrict__ in, float* __restrict__ out, int count)
{
    int idx = blockIdx.x * 256 + threadIdx.x;
    if (idx < count) out[idx] = tf32r(in[idx]);
}

// ---------------- h_attn = wV / (z + 1e-8) ----------------
__global__ void finalize_attn(const float* __restrict__ wV, const float* __restrict__ z,
                              float* __restrict__ hattn)
{
    int idx = blockIdx.x * blockDim.x + threadIdx.x;
    if (idx >= NN * 32) return;
    int n = idx >> 5;
    int head = (idx & 31) >> 2;
    float inv = 1.f / (z[(size_t)n * 8 + head] + 1e-8f);
    float4 v = ((const float4*)wV)[idx];
    v.x *= inv; v.y *= inv; v.z *= inv; v.w *= inv;
    ((float4*)hattn)[idx] = v;
}

// ---------------- launch ----------------
extern "C" void kernel_launch(void* const* d_in, const int* in_sizes, int n_in,
                              void* d_out, int out_size)
{
    const float* node_feats = (const float*)d_in[0];
    const float* edge_feats = (const float*)d_in[1];
    const int*   src        = (const int*)d_in[2];
    const int*   dst        = (const int*)d_in[3];
    const float* ln1n_w = (const float*)d_in[4];
    const float* ln1n_b = (const float*)d_in[5];
    const float* ln1e_w = (const float*)d_in[6];
    const float* ln1e_b = (const float*)d_in[7];
    const float* ln2n_w = (const float*)d_in[8];
    const float* ln2n_b = (const float*)d_in[9];
    const float* ln2e_w = (const float*)d_in[10];
    const float* ln2e_b = (const float*)d_in[11];
    const float* Wq = (const float*)d_in[12];
    const float* bq = (const float*)d_in[13];
    const float* Wk = (const float*)d_in[14];
    const float* bk = (const float*)d_in[15];
    const float* Wv = (const float*)d_in[16];
    const float* bv = (const float*)d_in[17];
    const float* We = (const float*)d_in[18];
    const float* be = (const float*)d_in[19];
    const float* Wo_n = (const float*)d_in[20];
    const float* bo_n = (const float*)d_in[21];
    const float* Wo_e = (const float*)d_in[22];
    const float* bo_e = (const float*)d_in[23];
    const float* mlp_n_w1 = (const float*)d_in[24];
    const float* mlp_n_w2 = (const float*)d_in[25];
    const float* mlp_e_w1 = (const float*)d_in[26];
    const float* mlp_e_w2 = (const float*)d_in[27];

    float* outh = (float*)d_out;
    float* oute = outh + (size_t)NN * DD;

    float *p_Q, *p_K, *p_V, *p_wV, *p_z, *p_hattn, *p_hmid, *p_emid, *p_hidn, *p_hide, *p_wT;
    cudaGetSymbolAddress((void**)&p_Q, g_Q);
    cudaGetSymbolAddress((void**)&p_K, g_K);
    cudaGetSymbolAddress((void**)&p_V, g_V);
    cudaGetSymbolAddress((void**)&p_wV, g_wV);
    cudaGetSymbolAddress((void**)&p_z, g_z);
    cudaGetSymbolAddress((void**)&p_hattn, g_hattn);
    cudaGetSymbolAddress((void**)&p_hmid, g_hmid);
    cudaGetSymbolAddress((void**)&p_emid, g_emid);
    cudaGetSymbolAddress((void**)&p_hidn, g_hid_n);
    cudaGetSymbolAddress((void**)&p_hide, g_hid_e);
    cudaGetSymbolAddress((void**)&p_wT, g_wT);

    cudaFuncSetAttribute(gemm5, cudaFuncAttributeMaxDynamicSharedMemorySize, SMEM_1);
    cudaFuncSetAttribute(attn5, cudaFuncAttributeMaxDynamicSharedMemorySize, SMEM_1);
    cudaFuncSetAttribute(qkv5, cudaFuncAttributeMaxDynamicSharedMemorySize, SMEM_2);

    cudaMemsetAsync(p_wV, 0, (size_t)NN * DD * sizeof(float));
    cudaMemsetAsync(p_z, 0, (size_t)NN * HH * sizeof(float));

    // weight prep
    int g16 = (16384 + 255) / 256, g32 = (32768 + 255) / 256;
    round_copy<<<g16, 256>>>(Wq, p_wT + OT_WQ, 16384);
    round_copy<<<g16, 256>>>(Wk, p_wT + OT_WK, 16384);
    round_copy<<<g16, 256>>>(Wv, p_wT + OT_WV, 16384);
    round_copy<<<g16, 256>>>(Wo_n, p_wT + OT_WON, 16384);
    round_copy<<<g16, 256>>>(Wo_e, p_wT + OT_WOE, 16384);
    round_copy<<<g16, 256>>>(We, p_wT + OT_WE, 16384);
    round_copy<<<g32, 256>>>(mlp_n_w1, p_wT + OT_W1N, 32768);
    round_copy<<<g32, 256>>>(mlp_n_w2, p_wT + OT_W2N, 32768);
    round_copy<<<g32, 256>>>(mlp_e_w1, p_wT + OT_W1E, 32768);
    round_copy<<<g32, 256>>>(mlp_e_w2, p_wT + OT_W2E, 32768);

    const int gN = (NN + 127) / 128;   // 391
    const int gE = EE / 128;           // 6250

    // QKV (LN1n fused, one kernel)
    qkv5<<<gN, 128, SMEM_2>>>(node_feats, p_wT, bq, bk, bv, ln1n_w, ln1n_b, p_Q, p_K, p_V);

    // fused edge attention + Wo_e + residual -> emid
    attn5<<<gE, 128, SMEM_1>>>(edge_feats, p_wT + OT_WE, p_wT + OT_WOE,
                               ln1e_w, ln1e_b, be, bo_e,
                               p_Q, p_K, p_V, src, dst, p_emid, p_wV, p_z);

    finalize_attn<<<(NN * 32 + 255) / 256, 256>>>(p_wV, p_z, p_hattn);

    // node chain
    gemm5<<<dim3(gN, 1), 128, SMEM_1>>>(p_hattn, p_wT + OT_WON, bo_n, nullptr, nullptr, node_feats, p_hmid, NN, 128, 128, F_BIAS | F_RESID);
    gemm5<<<dim3(gN, 2), 128, SMEM_1>>>(p_hmid, p_wT + OT_W1N, nullptr, ln2n_w, ln2n_b, nullptr, p_hidn, NN, 128, 256, F_SILU | F_LN);
    gemm5<<<dim3(gN, 1), 128, SMEM_1>>>(p_hidn, p_wT + OT_W2N, nullptr, nullptr, nullptr, p_hmid, outh, NN, 256, 128, F_RESID);

    // edge MLP
    gemm5<<<dim3(gE, 2), 128, SMEM_1>>>(p_emid, p_wT + OT_W1E, nullptr, ln2e_w, ln2e_b, nullptr, p_hide, EE, 128, 256, F_SILU | F_LN);
    gemm5<<<dim3(gE, 1), 128, SMEM_1>>>(p_hide, p_wT + OT_W2E, nullptr, nullptr, nullptr, p_emid, oute, EE, 256, 128, F_RESID);
}